// round 8
// baseline (speedup 1.0000x reference)
#include <cuda_runtime.h>
#include <cstdint>

// Shapes fixed by the reference:
//   x: [N, 128] f32, adj_row/adj_col: [E] int32-or-int64 (runtime detect),
//   adj_val: [E] f32, W: [128, 64] f32, b: [64] f32 -> out: [N, 64] f32
#define MAX_NODES 131072
#define E_CAP     1700000
#define F_IN  128
#define F_OUT 64
#define SCAN_CHUNK 1024
#define SCAN_MAXBLK 128

#define ROWS_PER_BLOCK 256      // gemm: rows per block (8 warps x 32 rows)
#define XS_STRIDE 132           // xs row stride (floats) — conflict-free A frags
#define WS_STRIDE 68            // W smem stride (floats) — conflict-free B frags
// dynamic smem: Whi + Wlo + xs
#define GEMM_SMEM_BYTES ((2 * F_IN * WS_STRIDE + ROWS_PER_BLOCK * XS_STRIDE) * 4)

// ---- static device scratch (no cudaMalloc allowed) ----
__device__ __align__(16) float g_xw[(size_t)MAX_NODES * F_OUT];
__device__ long long g_packed[E_CAP];      // lo32=col, hi32=val bits
__device__ int g_cnt[MAX_NODES];
__device__ int g_incl[MAX_NODES];
__device__ int g_blocktot[SCAN_MAXBLK];
__device__ int g_row_ptr[MAX_NODES + 1];
__device__ int g_cursor[MAX_NODES];
__device__ int g_idx64;

__device__ __forceinline__ int load_idx(const void* p, int e)
{
    return g_idx64 ? (int)((const long long*)p)[e] : ((const int*)p)[e];
}

__device__ __forceinline__ unsigned f2tf32(float f)
{
    unsigned u;
    asm("cvt.rna.tf32.f32 %0, %1;" : "=r"(u) : "f"(f));
    return u;
}

__device__ __forceinline__ void mma_tf32(float* d, const unsigned* a,
                                         unsigned b0, unsigned b1)
{
    asm volatile(
        "mma.sync.aligned.m16n8k8.row.col.f32.tf32.tf32.f32 "
        "{%0,%1,%2,%3}, {%4,%5,%6,%7}, {%8,%9}, {%0,%1,%2,%3};"
        : "+f"(d[0]), "+f"(d[1]), "+f"(d[2]), "+f"(d[3])
        : "r"(a[0]), "r"(a[1]), "r"(a[2]), "r"(a[3]), "r"(b0), "r"(b1));
}

// ---------------------------------------------------------------------------
// Kernel 1: prep = zero g_cnt (all blocks) + index-dtype detect (block 0).
// int64 indices (<2^31) have every odd 32-bit word zero; int32 data doesn't.
// ---------------------------------------------------------------------------
__global__ __launch_bounds__(256) void prep_kernel(
    const int* __restrict__ row_raw, int n_edges, int n_nodes)
{
    int i = blockIdx.x * blockDim.x + threadIdx.x;
    if (i < n_nodes) g_cnt[i] = 0;

    if (blockIdx.x == 0) {
        __shared__ int any_nonzero;
        int t = threadIdx.x;
        if (t == 0) any_nonzero = 0;
        __syncthreads();
        int limit = n_edges < 64 ? n_edges : 64;
        if (t < limit && row_raw[2 * t + 1] != 0)
            atomicOr(&any_nonzero, 1);
        __syncthreads();
        if (t == 0) g_idx64 = (any_nonzero == 0);
    }
}

// ---------------------------------------------------------------------------
// Kernel 2: fused TF32x3 tensor GEMM (xw = x @ W) + row histogram.
// Block 256 thr = 8 warps; warp computes 32 rows x 64 cols via 2 m-tiles x
// 8 n-tiles of mma.m16n8k8, 3 mma per tile (hi*hi + hi*lo + lo*hi).
// Histogram RED.adds are issued before the barrier and drain under the MMAs.
// ---------------------------------------------------------------------------
__global__ __launch_bounds__(256) void gemm_hist_kernel(
    const float* __restrict__ x, const float* __restrict__ W,
    float* __restrict__ xw,
    const void* __restrict__ adj_row,
    int n_nodes, int n_edges)
{
    extern __shared__ __align__(16) float smem[];
    float* Whi = smem;                                   // [128][68]
    float* Wlo = smem + F_IN * WS_STRIDE;                // [128][68]
    float* xs  = smem + 2 * F_IN * WS_STRIDE;            // [256][132]

    const int tid  = threadIdx.x;
    const int row0 = blockIdx.x * ROWS_PER_BLOCK;

    // Stage W -> split into tf32 hi / residual lo.
    for (int i = tid; i < F_IN * F_OUT; i += 256) {
        int k = i >> 6, n = i & 63;
        float w = W[i];
        float whi = __uint_as_float(f2tf32(w));
        Whi[k * WS_STRIDE + n] = whi;
        Wlo[k * WS_STRIDE + n] = w - whi;
    }

    // Stage x tile (coalesced float4; rows beyond n_nodes zeroed).
    for (int i = tid; i < ROWS_PER_BLOCK * F_IN / 4; i += 256) {
        int r = i / (F_IN / 4);
        int c = i % (F_IN / 4);
        int gr = row0 + r;
        float4 v = make_float4(0.f, 0.f, 0.f, 0.f);
        if (gr < n_nodes)
            v = ((const float4*)(x + (size_t)gr * F_IN))[c];
        ((float4*)(xs + r * XS_STRIDE))[c] = v;
    }

    // Histogram (independent of GEMM data; overlaps with MMA phase).
    {
        int stride = gridDim.x * 256;
        for (int e = blockIdx.x * 256 + tid; e < n_edges; e += stride) {
            int r = load_idx(adj_row, e);
            if ((unsigned)r < (unsigned)n_nodes)
                atomicAdd(&g_cnt[r], 1);
        }
    }
    __syncthreads();

    const int lane = tid & 31;
    const int warp = tid >> 5;
    const int grp  = lane >> 2;      // 0..7
    const int tc   = lane & 3;       // 0..3
    const int wrow = warp * 32;      // block-local first row of this warp

    float acc[2][8][4];
    #pragma unroll
    for (int mt = 0; mt < 2; mt++)
        #pragma unroll
        for (int nt = 0; nt < 8; nt++)
            #pragma unroll
            for (int j = 0; j < 4; j++)
                acc[mt][nt][j] = 0.f;

    #pragma unroll 2
    for (int ks = 0; ks < F_IN / 8; ks++) {
        int k0 = ks * 8;

        unsigned ahi[2][4], alo[2][4];
        #pragma unroll
        for (int mt = 0; mt < 2; mt++) {
            int rb = wrow + mt * 16 + grp;
            float a0 = xs[(rb + 0) * XS_STRIDE + k0 + tc];
            float a1 = xs[(rb + 8) * XS_STRIDE + k0 + tc];
            float a2 = xs[(rb + 0) * XS_STRIDE + k0 + tc + 4];
            float a3 = xs[(rb + 8) * XS_STRIDE + k0 + tc + 4];
            ahi[mt][0] = f2tf32(a0); alo[mt][0] = f2tf32(a0 - __uint_as_float(ahi[mt][0]));
            ahi[mt][1] = f2tf32(a1); alo[mt][1] = f2tf32(a1 - __uint_as_float(ahi[mt][1]));
            ahi[mt][2] = f2tf32(a2); alo[mt][2] = f2tf32(a2 - __uint_as_float(ahi[mt][2]));
            ahi[mt][3] = f2tf32(a3); alo[mt][3] = f2tf32(a3 - __uint_as_float(ahi[mt][3]));
        }

        #pragma unroll
        for (int nt = 0; nt < 8; nt++) {
            int n = nt * 8 + grp;
            unsigned bh0 = __float_as_uint(Whi[(k0 + tc) * WS_STRIDE + n]);
            unsigned bh1 = __float_as_uint(Whi[(k0 + tc + 4) * WS_STRIDE + n]);
            unsigned bl0 = __float_as_uint(Wlo[(k0 + tc) * WS_STRIDE + n]);
            unsigned bl1 = __float_as_uint(Wlo[(k0 + tc + 4) * WS_STRIDE + n]);
            // W staged via f2tf32 already; lo is exact residual -> convert:
            bl0 = f2tf32(__uint_as_float(bl0));
            bl1 = f2tf32(__uint_as_float(bl1));
            #pragma unroll
            for (int mt = 0; mt < 2; mt++) {
                mma_tf32(acc[mt][nt], ahi[mt], bh0, bh1);
                mma_tf32(acc[mt][nt], ahi[mt], bl0, bl1);
                mma_tf32(acc[mt][nt], alo[mt], bh0, bh1);
            }
        }
    }

    // Epilogue: c0/c1 at (grp, 2*tc, 2*tc+1); c2/c3 at (grp+8, same cols).
    #pragma unroll
    for (int mt = 0; mt < 2; mt++) {
        int r_lo = row0 + wrow + mt * 16 + grp;
        int r_hi = r_lo + 8;
        #pragma unroll
        for (int nt = 0; nt < 8; nt++) {
            int col = nt * 8 + tc * 2;
            if (r_lo < n_nodes)
                *(float2*)(xw + (size_t)r_lo * F_OUT + col) =
                    make_float2(acc[mt][nt][0], acc[mt][nt][1]);
            if (r_hi < n_nodes)
                *(float2*)(xw + (size_t)r_hi * F_OUT + col) =
                    make_float2(acc[mt][nt][2], acc[mt][nt][3]);
        }
    }
}

// ---------------------------------------------------------------------------
// CSR scan / finalize / pack.
// ---------------------------------------------------------------------------
__global__ __launch_bounds__(SCAN_CHUNK) void scan_part_kernel(int n)
{
    __shared__ int s[SCAN_CHUNK];
    int t = threadIdx.x;
    int i = blockIdx.x * SCAN_CHUNK + t;
    int v = (i < n) ? g_cnt[i] : 0;
    s[t] = v;
    __syncthreads();
    #pragma unroll
    for (int off = 1; off < SCAN_CHUNK; off <<= 1) {
        int add = (t >= off) ? s[t - off] : 0;
        __syncthreads();
        s[t] += add;
        __syncthreads();
    }
    if (i < n) g_incl[i] = s[t];
    if (t == SCAN_CHUNK - 1) g_blocktot[blockIdx.x] = s[t];
}

__global__ __launch_bounds__(SCAN_MAXBLK) void scan_top_kernel(int nblocks)
{
    __shared__ int s[SCAN_MAXBLK];
    int t = threadIdx.x;
    int v = (t < nblocks) ? g_blocktot[t] : 0;
    s[t] = v;
    __syncthreads();
    #pragma unroll
    for (int off = 1; off < SCAN_MAXBLK; off <<= 1) {
        int add = (t >= off) ? s[t - off] : 0;
        __syncthreads();
        s[t] += add;
        __syncthreads();
    }
    if (t < nblocks) g_blocktot[t] = s[t] - v;   // exclusive
}

__global__ void finalize_kernel(int n)
{
    int i = blockIdx.x * blockDim.x + threadIdx.x;
    if (i >= n) return;
    int inc = g_incl[i] + g_blocktot[i / SCAN_CHUNK];
    g_row_ptr[i + 1] = inc;
    g_cursor[i] = inc - g_cnt[i];
    if (i == 0) g_row_ptr[0] = 0;
}

__global__ void pack_kernel(const void* __restrict__ adj_row,
                            const void* __restrict__ adj_col,
                            const float* __restrict__ adj_val,
                            int n_edges, int n_nodes)
{
    int e = blockIdx.x * blockDim.x + threadIdx.x;
    if (e >= n_edges) return;
    int r = load_idx(adj_row, e);
    int c = load_idx(adj_col, e);
    if ((unsigned)r >= (unsigned)n_nodes || (unsigned)c >= (unsigned)n_nodes)
        return;
    float v = adj_val[e];
    int pos = atomicAdd(&g_cursor[r], 1);
    if (pos < E_CAP)
        g_packed[pos] = ((long long)__float_as_int(v) << 32) | (unsigned)c;
}

// ---------------------------------------------------------------------------
// Aggregate (pull): 16-lane half-warp per row; bias fused; no atomics.
// ---------------------------------------------------------------------------
__global__ __launch_bounds__(256) void aggregate_kernel(
    const float* __restrict__ xw, const float* __restrict__ b,
    float* __restrict__ out, int n_nodes)
{
    int g  = blockIdx.x * blockDim.x + threadIdx.x;
    int r  = g >> 4;
    int c4 = g & 15;
    if (r >= n_nodes) return;

    int i   = g_row_ptr[r];
    int end = g_row_ptr[r + 1];

    float4 acc = ((const float4*)b)[c4];
    const float4* xw4 = (const float4*)xw;

    for (; i + 4 <= end; i += 4) {
        long long p0 = g_packed[i + 0];
        long long p1 = g_packed[i + 1];
        long long p2 = g_packed[i + 2];
        long long p3 = g_packed[i + 3];
        int   c0 = (int)p0;  float v0 = __int_as_float((int)(p0 >> 32));
        int   c1 = (int)p1;  float v1 = __int_as_float((int)(p1 >> 32));
        int   c2 = (int)p2;  float v2 = __int_as_float((int)(p2 >> 32));
        int   c3 = (int)p3;  float v3 = __int_as_float((int)(p3 >> 32));
        float4 m0 = xw4[(size_t)c0 * 16 + c4];
        float4 m1 = xw4[(size_t)c1 * 16 + c4];
        float4 m2 = xw4[(size_t)c2 * 16 + c4];
        float4 m3 = xw4[(size_t)c3 * 16 + c4];
        acc.x += v0 * m0.x + v1 * m1.x + v2 * m2.x + v3 * m3.x;
        acc.y += v0 * m0.y + v1 * m1.y + v2 * m2.y + v3 * m3.y;
        acc.z += v0 * m0.z + v1 * m1.z + v2 * m2.z + v3 * m3.z;
        acc.w += v0 * m0.w + v1 * m1.w + v2 * m2.w + v3 * m3.w;
    }
    for (; i < end; i++) {
        long long p = g_packed[i];
        int   c = (int)p;
        float v = __int_as_float((int)(p >> 32));
        float4 m = xw4[(size_t)c * 16 + c4];
        acc.x += v * m.x;  acc.y += v * m.y;
        acc.z += v * m.z;  acc.w += v * m.w;
    }

    ((float4*)out)[(size_t)r * 16 + c4] = acc;
}

// ---------------------------------------------------------------------------
// Launch. Inputs (metadata order): x, adj_row, adj_col, adj_val, W, b
// ---------------------------------------------------------------------------
extern "C" void kernel_launch(void* const* d_in, const int* in_sizes, int n_in,
                              void* d_out, int out_size)
{
    const float* x       = (const float*)d_in[0];
    const void*  adj_row = d_in[1];
    const void*  adj_col = d_in[2];
    const float* adj_val = (const float*)d_in[3];
    const float* W       = (const float*)d_in[4];
    const float* b       = (const float*)d_in[5];
    float*       out     = (float*)d_out;

    const int n_nodes = in_sizes[0] / F_IN;
    const int n_edges = in_sizes[3];

    float* xw;
    cudaGetSymbolAddress((void**)&xw, g_xw);

    cudaFuncSetAttribute(gemm_hist_kernel,
                         cudaFuncAttributeMaxDynamicSharedMemorySize,
                         GEMM_SMEM_BYTES);

    const int EB = (n_edges + 255) / 256;
    const int NB = (n_nodes + 255) / 256;
    const int SCANB = (n_nodes + SCAN_CHUNK - 1) / SCAN_CHUNK;
    const int GB = (n_nodes + ROWS_PER_BLOCK - 1) / ROWS_PER_BLOCK;

    // 1) zero counters + index dtype detect
    prep_kernel<<<NB, 256>>>((const int*)adj_row, n_edges, n_nodes);

    // 2) fused tensor GEMM + histogram
    gemm_hist_kernel<<<GB, 256, GEMM_SMEM_BYTES>>>(x, W, xw, adj_row,
                                                   n_nodes, n_edges);

    // 3) CSR scan + pack
    scan_part_kernel<<<SCANB, SCAN_CHUNK>>>(n_nodes);
    scan_top_kernel<<<1, SCAN_MAXBLK>>>(SCANB);
    finalize_kernel<<<NB, 256>>>(n_nodes);
    pack_kernel<<<EB, 256>>>(adj_row, adj_col, adj_val, n_edges, n_nodes);

    // 4) pull-based aggregate (bias fused)
    aggregate_kernel<<<(n_nodes * 16 + 255) / 256, 256>>>(xw, b, out, n_nodes);
}